// round 3
// baseline (speedup 1.0000x reference)
#include <cuda_runtime.h>

#define NN 4096
#define BB 8
#define CHUNK 64              // senders per block (32 pairs)
#define NGROUP (NN / CHUNK)   // 64 sender groups
#define TPB 256

// strength(v) = (e^v - e^-1)/(e - e^-1) = C1*e^v - C2
#define C1f 0.4254590641196608f
#define C2f 0.1565176423029702f
#define L2E 1.4426950408889634f

typedef unsigned long long u64;

// Scratch: [NGROUP][B][N] = 8 MB (L2-resident between kernels)
__device__ float g_partial[NGROUP * BB * NN];

// ---------- f32x2 helpers ----------
__device__ __forceinline__ u64 pack2(float lo, float hi) {
    u64 r; asm("mov.b64 %0, {%1, %2};" : "=l"(r) : "f"(lo), "f"(hi)); return r;
}
__device__ __forceinline__ void unpack2(u64 v, float& lo, float& hi) {
    asm("mov.b64 {%0, %1}, %2;" : "=f"(lo), "=f"(hi) : "l"(v));
}
__device__ __forceinline__ u64 fma2(u64 a, u64 b, u64 c) {
    u64 d; asm("fma.rn.f32x2 %0, %1, %2, %3;" : "=l"(d) : "l"(a), "l"(b), "l"(c)); return d;
}
__device__ __forceinline__ u64 mul2(u64 a, u64 b) {
    u64 d; asm("mul.rn.f32x2 %0, %1, %2;" : "=l"(d) : "l"(a), "l"(b)); return d;
}
__device__ __forceinline__ float ex2a(float x) {
    float r; asm("ex2.approx.f32 %0, %1;" : "=f"(r) : "f"(x)); return r;
}
__device__ __forceinline__ float rsqa(float x) {
    float r; asm("rsqrt.approx.f32 %0, %1;" : "=f"(r) : "f"(x)); return r;
}

// Shared layout per sender-pair p (senders A=2p, B=2p+1):
//   shP[p][0] = (pxA,pxB, pyA,pyB)
//   shP[p][1] = (pzA,pzB, oxA*L2E, oxB*L2E)
//   shP[p][2] = (oyA*L2E, oyB*L2E, ozA*L2E, ozB*L2E)
// Per sender s: shX[s][h] = x[4h..4h+3][s]
__global__ __launch_bounds__(TPB, 2) void pair_kernel(
    const float* __restrict__ x,
    const float* __restrict__ position,
    const float* __restrict__ indir,
    const float* __restrict__ outdir)
{
    __shared__ float4 shP[CHUNK / 2][3];
    __shared__ float4 shX[CHUNK][2];

    const int tid = threadIdx.x;
    const int j   = blockIdx.x * TPB + tid;   // receiver
    const int i0  = blockIdx.y * CHUNK;       // sender base

    if (tid < 128) {
        const int s = tid >> 1, h = tid & 1, i = i0 + s;
        shX[s][h] = make_float4(x[(4 * h + 0) * NN + i], x[(4 * h + 1) * NN + i],
                                x[(4 * h + 2) * NN + i], x[(4 * h + 3) * NN + i]);
    } else if (tid < 224) {
        const int t = tid - 128;
        const int pr = t / 3, f = t % 3;
        const int iA = i0 + 2 * pr, iB = iA + 1;
        float4 v;
        if (f == 0)
            v = make_float4(position[iA * 3 + 0], position[iB * 3 + 0],
                            position[iA * 3 + 1], position[iB * 3 + 1]);
        else if (f == 1)
            v = make_float4(position[iA * 3 + 2], position[iB * 3 + 2],
                            outdir[iA * 3 + 0] * L2E, outdir[iB * 3 + 0] * L2E);
        else
            v = make_float4(outdir[iA * 3 + 1] * L2E, outdir[iB * 3 + 1] * L2E,
                            outdir[iA * 3 + 2] * L2E, outdir[iB * 3 + 2] * L2E);
        shP[pr][f] = v;
    }

    // Receiver invariants (packed as (v,v))
    const float pjx = position[j * 3 + 0];
    const float pjy = position[j * 3 + 1];
    const float pjz = position[j * 3 + 2];
    const u64 pjx2 = pack2(pjx, pjx);
    const u64 pjy2 = pack2(pjy, pjy);
    const u64 pjz2 = pack2(pjz, pjz);
    const float inx = indir[j * 3 + 0] * L2E;
    const float iny = indir[j * 3 + 1] * L2E;
    const float inz = indir[j * 3 + 2] * L2E;
    const u64 inx2 = pack2(inx, inx);
    const u64 iny2 = pack2(iny, iny);
    const u64 inz2 = pack2(inz, inz);
    const u64 neg1 = pack2(-1.f, -1.f);
    const u64 c12  = pack2(C1f, C1f);
    const u64 nc22 = pack2(-C2f, -C2f);

    __syncthreads();

    u64 acc0 = 0, acc1 = 0, acc2 = 0, acc3 = 0;

#pragma unroll 4
    for (int p = 0; p < CHUNK / 2; p++) {
        const ulonglong2 P0 = *reinterpret_cast<const ulonglong2*>(&shP[p][0]);
        const ulonglong2 P1 = *reinterpret_cast<const ulonglong2*>(&shP[p][1]);
        const ulonglong2 P2 = *reinterpret_cast<const ulonglong2*>(&shP[p][2]);

        // delta = pos_j - pos_i   (for senders A,B packed)
        const u64 dx = fma2(P0.x, neg1, pjx2);
        const u64 dy = fma2(P0.y, neg1, pjy2);
        const u64 dz = fma2(P1.x, neg1, pjz2);

        const u64 n2 = fma2(dx, dx, fma2(dy, dy, mul2(dz, dz)));
        float nA, nB; unpack2(n2, nA, nB);
        const u64 rn = pack2(rsqa(fmaxf(nA, 1e-5f)), rsqa(fmaxf(nB, 1e-5f)));

        // dots (dirs pre-scaled by log2(e))
        const u64 da = fma2(dx, P1.y, fma2(dy, P2.x, mul2(dz, P2.y)));
        const u64 db = fma2(dx, inx2, fma2(dy, iny2, mul2(dz, inz2)));

        const u64 ta = mul2(da, rn);
        const u64 tb = mul2(db, rn);
        float taA, taB, tbA, tbB;
        unpack2(ta, taA, taB);
        unpack2(tb, tbA, tbB);
        const u64 ea = pack2(ex2a(taA), ex2a(taB));
        const u64 eb = pack2(ex2a(tbA), ex2a(tbB));

        const u64 sa = fma2(c12, ea, nc22);
        const u64 sb = fma2(c12, eb, nc22);
        const u64 g  = mul2(sa, sb);
        float gA, gB; unpack2(g, gA, gB);
        const u64 ggA = pack2(gA, gA);
        const u64 ggB = pack2(gB, gB);

        const ulonglong2 XA0 = *reinterpret_cast<const ulonglong2*>(&shX[2 * p][0]);
        const ulonglong2 XA1 = *reinterpret_cast<const ulonglong2*>(&shX[2 * p][1]);
        const ulonglong2 XB0 = *reinterpret_cast<const ulonglong2*>(&shX[2 * p + 1][0]);
        const ulonglong2 XB1 = *reinterpret_cast<const ulonglong2*>(&shX[2 * p + 1][1]);

        acc0 = fma2(ggA, XA0.x, acc0);  acc0 = fma2(ggB, XB0.x, acc0);
        acc1 = fma2(ggA, XA0.y, acc1);  acc1 = fma2(ggB, XB0.y, acc1);
        acc2 = fma2(ggA, XA1.x, acc2);  acc2 = fma2(ggB, XB1.x, acc2);
        acc3 = fma2(ggA, XA1.y, acc3);  acc3 = fma2(ggB, XB1.y, acc3);
    }

    float* outp = g_partial + (size_t)(blockIdx.y * BB) * NN + j;
    float v0, v1;
    unpack2(acc0, v0, v1); outp[0 * NN] = v0; outp[1 * NN] = v1;
    unpack2(acc1, v0, v1); outp[2 * NN] = v0; outp[3 * NN] = v1;
    unpack2(acc2, v0, v1); outp[4 * NN] = v0; outp[5 * NN] = v1;
    unpack2(acc3, v0, v1); outp[6 * NN] = v0; outp[7 * NN] = v1;
}

// Warp-per-output reduce: 32768 outputs, 1 warp each.
__global__ __launch_bounds__(256) void reduce_kernel(
    const float* __restrict__ power,
    const float* __restrict__ bias,
    float* __restrict__ out)
{
    const int warp = (blockIdx.x * 256 + threadIdx.x) >> 5;  // output index
    const int lane = threadIdx.x & 31;
    const int b = warp >> 12;
    const int j = warp & (NN - 1);

    float s = g_partial[(size_t)(lane * BB + b) * NN + j]
            + g_partial[(size_t)((lane + 32) * BB + b) * NN + j];
#pragma unroll
    for (int off = 16; off > 0; off >>= 1)
        s += __shfl_down_sync(0xFFFFFFFFu, s, off);

    if (lane == 0) {
        const float z = fmaf(s, power[j], -bias[j]);
        out[warp] = (z > 0.f) ? z : expm1f(z);
    }
}

extern "C" void kernel_launch(void* const* d_in, const int* in_sizes, int n_in,
                              void* d_out, int out_size)
{
    const float* x        = (const float*)d_in[0];
    const float* position = (const float*)d_in[1];
    const float* indir    = (const float*)d_in[2];
    const float* outdir   = (const float*)d_in[3];
    const float* power    = (const float*)d_in[4];
    const float* bias     = (const float*)d_in[5];
    float* out = (float*)d_out;

    dim3 grid(NN / TPB, NGROUP);
    pair_kernel<<<grid, TPB>>>(x, position, indir, outdir);
    reduce_kernel<<<(BB * NN * 32) / 256, 256>>>(power, bias, out);
}

// round 13
// speedup vs baseline: 1.2672x; 1.2672x over previous
#include <cuda_runtime.h>

#define NN 4096
#define BB 8
#define CHUNK 64              // senders per block (32 pairs)
#define NGROUP (NN / CHUNK)   // 64 sender groups
#define TPB 256

// strength(v) = (e^v - e^-1)/(e - e^-1) = C1*e^v - C2
#define C1f 0.4254590641196608f
#define C2f 0.1565176423029702f
#define L2E 1.4426950408889634f

typedef unsigned long long u64;

// Scratch: [NGROUP][B][N] = 8 MB (L2-resident between kernels)
__device__ float g_partial[NGROUP * BB * NN];

// ---------- f32x2 helpers ----------
__device__ __forceinline__ u64 pack2(float lo, float hi) {
    u64 r; asm("mov.b64 %0, {%1, %2};" : "=l"(r) : "f"(lo), "f"(hi)); return r;
}
__device__ __forceinline__ void unpack2(u64 v, float& lo, float& hi) {
    asm("mov.b64 {%0, %1}, %2;" : "=f"(lo), "=f"(hi) : "l"(v));
}
__device__ __forceinline__ u64 fma2(u64 a, u64 b, u64 c) {
    u64 d; asm("fma.rn.f32x2 %0, %1, %2, %3;" : "=l"(d) : "l"(a), "l"(b), "l"(c)); return d;
}
__device__ __forceinline__ u64 mul2(u64 a, u64 b) {
    u64 d; asm("mul.rn.f32x2 %0, %1, %2;" : "=l"(d) : "l"(a), "l"(b)); return d;
}
__device__ __forceinline__ u64 add2(u64 a, u64 b) {
    u64 d; asm("add.rn.f32x2 %0, %1, %2;" : "=l"(d) : "l"(a), "l"(b)); return d;
}
__device__ __forceinline__ float ex2a(float x) {
    float r; asm("ex2.approx.f32 %0, %1;" : "=f"(r) : "f"(x)); return r;
}
__device__ __forceinline__ float rsqa(float x) {
    float r; asm("rsqrt.approx.f32 %0, %1;" : "=f"(r) : "f"(x)); return r;
}

// Shared layout per sender-pair p (senders A=2p, B=2p+1):
//   shP[p][0] = (-pxA,-pxB, -pyA,-pyB)            (negated positions)
//   shP[p][1] = (-pzA,-pzB, oxA*L2E, oxB*L2E)
//   shP[p][2] = (oyA*L2E, oyB*L2E, ozA*L2E, ozB*L2E)
// X pair-packed: shXP[p][q] = (x[2q][A], x[2q][B], x[2q+1][A], x[2q+1][B]), q=0..3
__global__ __launch_bounds__(TPB, 3) void pair_kernel(
    const float* __restrict__ x,
    const float* __restrict__ position,
    const float* __restrict__ indir,
    const float* __restrict__ outdir)
{
    __shared__ float4 shP[CHUNK / 2][3];
    __shared__ float4 shXP[CHUNK / 2][4];

    const int tid = threadIdx.x;
    const int j   = blockIdx.x * TPB + tid;   // receiver
    const int i0  = blockIdx.y * CHUNK;       // sender base

    if (tid < 128) {
        const int p = tid >> 2, q = tid & 3;
        const int iA = i0 + 2 * p, iB = iA + 1;
        shXP[p][q] = make_float4(x[(2 * q + 0) * NN + iA], x[(2 * q + 0) * NN + iB],
                                 x[(2 * q + 1) * NN + iA], x[(2 * q + 1) * NN + iB]);
    } else if (tid < 224) {
        const int t = tid - 128;
        const int pr = t / 3, f = t % 3;
        const int iA = i0 + 2 * pr, iB = iA + 1;
        float4 v;
        if (f == 0)
            v = make_float4(-position[iA * 3 + 0], -position[iB * 3 + 0],
                            -position[iA * 3 + 1], -position[iB * 3 + 1]);
        else if (f == 1)
            v = make_float4(-position[iA * 3 + 2], -position[iB * 3 + 2],
                            outdir[iA * 3 + 0] * L2E, outdir[iB * 3 + 0] * L2E);
        else
            v = make_float4(outdir[iA * 3 + 1] * L2E, outdir[iB * 3 + 1] * L2E,
                            outdir[iA * 3 + 2] * L2E, outdir[iB * 3 + 2] * L2E);
        shP[pr][f] = v;
    }

    // Receiver invariants (packed as (v,v))
    const float pjx = position[j * 3 + 0];
    const float pjy = position[j * 3 + 1];
    const float pjz = position[j * 3 + 2];
    const u64 pjx2 = pack2(pjx, pjx);
    const u64 pjy2 = pack2(pjy, pjy);
    const u64 pjz2 = pack2(pjz, pjz);
    const float inx = indir[j * 3 + 0] * L2E;
    const float iny = indir[j * 3 + 1] * L2E;
    const float inz = indir[j * 3 + 2] * L2E;
    const u64 inx2 = pack2(inx, inx);
    const u64 iny2 = pack2(iny, iny);
    const u64 inz2 = pack2(inz, inz);
    const u64 c12  = pack2(C1f, C1f);
    const u64 nc22 = pack2(-C2f, -C2f);

    __syncthreads();

    // acc_h = (sum over even senders of g*x[h], sum over odd senders of g*x[h])
    u64 acc0 = 0, acc1 = 0, acc2 = 0, acc3 = 0;
    u64 acc4 = 0, acc5 = 0, acc6 = 0, acc7 = 0;

#pragma unroll 2
    for (int p = 0; p < CHUNK / 2; p++) {
        const ulonglong2 P0 = *reinterpret_cast<const ulonglong2*>(&shP[p][0]);
        const ulonglong2 P1 = *reinterpret_cast<const ulonglong2*>(&shP[p][1]);
        const ulonglong2 P2 = *reinterpret_cast<const ulonglong2*>(&shP[p][2]);

        // delta = pos_j + (-pos_i)   senders A,B packed
        const u64 dx = add2(pjx2, P0.x);
        const u64 dy = add2(pjy2, P0.y);
        const u64 dz = add2(pjz2, P1.x);

        const u64 n2 = fma2(dx, dx, fma2(dy, dy, mul2(dz, dz)));
        float nA, nB; unpack2(n2, nA, nB);
        const u64 rn = pack2(rsqa(fmaxf(nA, 1e-5f)), rsqa(fmaxf(nB, 1e-5f)));

        // dots (dirs pre-scaled by log2(e))
        const u64 da = fma2(dx, P1.y, fma2(dy, P2.x, mul2(dz, P2.y)));
        const u64 db = fma2(dx, inx2, fma2(dy, iny2, mul2(dz, inz2)));

        const u64 ta = mul2(da, rn);
        const u64 tb = mul2(db, rn);
        float taA, taB, tbA, tbB;
        unpack2(ta, taA, taB);
        unpack2(tb, tbA, tbB);
        const u64 ea = pack2(ex2a(taA), ex2a(taB));
        const u64 eb = pack2(ex2a(tbA), ex2a(tbB));

        const u64 sa = fma2(c12, ea, nc22);
        const u64 sb = fma2(c12, eb, nc22);
        const u64 g  = mul2(sa, sb);          // (gA, gB) — used directly

        const ulonglong2 X0 = *reinterpret_cast<const ulonglong2*>(&shXP[p][0]);
        const ulonglong2 X1 = *reinterpret_cast<const ulonglong2*>(&shXP[p][1]);
        const ulonglong2 X2 = *reinterpret_cast<const ulonglong2*>(&shXP[p][2]);
        const ulonglong2 X3 = *reinterpret_cast<const ulonglong2*>(&shXP[p][3]);

        acc0 = fma2(g, X0.x, acc0);   // h=0 : (gA*xA0, gB*xB0)
        acc1 = fma2(g, X0.y, acc1);   // h=1
        acc2 = fma2(g, X1.x, acc2);   // h=2
        acc3 = fma2(g, X1.y, acc3);   // h=3
        acc4 = fma2(g, X2.x, acc4);   // h=4
        acc5 = fma2(g, X2.y, acc5);   // h=5
        acc6 = fma2(g, X3.x, acc6);   // h=6
        acc7 = fma2(g, X3.y, acc7);   // h=7
    }

    float* outp = g_partial + (size_t)(blockIdx.y * BB) * NN + j;
    float lo, hi;
    unpack2(acc0, lo, hi); outp[0 * NN] = lo + hi;
    unpack2(acc1, lo, hi); outp[1 * NN] = lo + hi;
    unpack2(acc2, lo, hi); outp[2 * NN] = lo + hi;
    unpack2(acc3, lo, hi); outp[3 * NN] = lo + hi;
    unpack2(acc4, lo, hi); outp[4 * NN] = lo + hi;
    unpack2(acc5, lo, hi); outp[5 * NN] = lo + hi;
    unpack2(acc6, lo, hi); outp[6 * NN] = lo + hi;
    unpack2(acc7, lo, hi); outp[7 * NN] = lo + hi;
}

// Reduce: each warp covers 8 consecutive outputs; lane = sub*8 + joff.
// Loads coalesced in j (32B runs), MLP=16 per thread.
__global__ __launch_bounds__(256) void reduce_kernel(
    const float* __restrict__ power,
    const float* __restrict__ bias,
    float* __restrict__ out)
{
    const int t    = blockIdx.x * 256 + threadIdx.x;
    const int warp = t >> 5;
    const int lane = threadIdx.x & 31;
    const int sub  = lane >> 3;              // 0..3  → chunk quarter
    const int o    = warp * 8 + (lane & 7);  // output index (b,j)
    const int b    = o >> 12;
    const int j    = o & (NN - 1);

    const float* base = g_partial + (size_t)b * NN + j;
    float s = 0.f;
#pragma unroll
    for (int cc = 0; cc < 16; cc++) {
        const int c = sub * 16 + cc;
        s += base[(size_t)c * BB * NN];
    }
    s += __shfl_down_sync(0xFFFFFFFFu, s, 8);
    s += __shfl_down_sync(0xFFFFFFFFu, s, 16);

    if (lane < 8) {
        const float z = fmaf(s, power[j], -bias[j]);
        out[o] = (z > 0.f) ? z : expm1f(z);
    }
}

extern "C" void kernel_launch(void* const* d_in, const int* in_sizes, int n_in,
                              void* d_out, int out_size)
{
    const float* x        = (const float*)d_in[0];
    const float* position = (const float*)d_in[1];
    const float* indir    = (const float*)d_in[2];
    const float* outdir   = (const float*)d_in[3];
    const float* power    = (const float*)d_in[4];
    const float* bias     = (const float*)d_in[5];
    float* out = (float*)d_out;

    dim3 grid(NN / TPB, NGROUP);
    pair_kernel<<<grid, TPB>>>(x, position, indir, outdir);
    // 32768 outputs * 4 sub-sums = 131072 threads
    reduce_kernel<<<(BB * NN * 4) / 256, 256>>>(power, bias, out);
}